// round 4
// baseline (speedup 1.0000x reference)
#include <cuda_runtime.h>
#include <cuda_fp16.h>
#include <cstdint>
#include <cstddef>

#define MM 8192
#define KK 4096
#define OO 4096

#define BM 128
#define BN 256
#define BK 32
#define KITERS (KK / BK)        // 128
#define STAGES 3
#define ROWPAD 40               // halves per row (32 data + 8 pad) -> conflict-free ldmatrix
#define A_STAGE_BYTES (BM * ROWPAD * 2)           // 10240
#define B_STAGE_BYTES (BN * ROWPAD * 2)           // 20480
#define STAGE_BYTES   (A_STAGE_BYTES + B_STAGE_BYTES)  // 30720
#define SMEM_BYTES    (STAGES * STAGE_BYTES)      // 92160

// Scratch (device globals only -- no allocation allowed)
__device__ __half g_W[(size_t)OO * KK];   // 32 MB dense ternary weights (fp16 exact)
__device__ __half g_A[(size_t)MM * KK];   // 64 MB x in fp16

// ---------------- PTX helpers (base sm_103 features only) ----------------
__device__ __forceinline__ uint32_t smem_u32(const void* p) {
    uint32_t a;
    asm("{ .reg .u64 t; cvta.to.shared.u64 t, %1; cvt.u32.u64 %0, t; }" : "=r"(a) : "l"(p));
    return a;
}
#define CP16(dst, src) \
    asm volatile("cp.async.cg.shared.global [%0], [%1], 16;" :: "r"(dst), "l"(src) : "memory")
#define CP_COMMIT() asm volatile("cp.async.commit_group;" ::: "memory")
#define CP_WAIT(n)  asm volatile("cp.async.wait_group %0;" :: "n"(n) : "memory")

__device__ __forceinline__ void ldsm_x4(uint32_t& r0, uint32_t& r1, uint32_t& r2, uint32_t& r3,
                                        uint32_t addr) {
    asm volatile("ldmatrix.sync.aligned.m8n8.x4.shared.b16 {%0,%1,%2,%3}, [%4];"
                 : "=r"(r0), "=r"(r1), "=r"(r2), "=r"(r3) : "r"(addr));
}
__device__ __forceinline__ void mma16816(float* c, const uint32_t* a, const uint32_t* b) {
    asm volatile(
        "mma.sync.aligned.m16n8k16.row.col.f32.f16.f16.f32 "
        "{%0,%1,%2,%3}, {%4,%5,%6,%7}, {%8,%9}, {%0,%1,%2,%3};"
        : "+f"(c[0]), "+f"(c[1]), "+f"(c[2]), "+f"(c[3])
        : "r"(a[0]), "r"(a[1]), "r"(a[2]), "r"(a[3]), "r"(b[0]), "r"(b[1]));
}

// ---------------- Kernel 1: unpack ternary -> fp16 W ----------------
__global__ void unpack_w_kernel(const int* __restrict__ nz, const int* __restrict__ sgn) {
    int idx = blockIdx.x * 256 + threadIdx.x;      // word index, OO*KK/32 total
    uint32_t nzv = (uint32_t)nz[idx];
    uint32_t sgv = (uint32_t)sgn[idx];
    uint32_t packed[16];
#pragma unroll
    for (int j = 0; j < 16; j++) {
        uint32_t lo = ((nzv >> (2*j)) & 1u)   ? (((sgv >> (2*j)) & 1u)   ? 0xBC00u : 0x3C00u) : 0u;
        uint32_t hi = ((nzv >> (2*j+1)) & 1u) ? (((sgv >> (2*j+1)) & 1u) ? 0xBC00u : 0x3C00u) : 0u;
        packed[j] = lo | (hi << 16);
    }
    uint4* dst = reinterpret_cast<uint4*>(g_W + (size_t)idx * 32);
#pragma unroll
    for (int j = 0; j < 4; j++)
        dst[j] = make_uint4(packed[4*j], packed[4*j+1], packed[4*j+2], packed[4*j+3]);
}

// ---------------- Kernel 2: x fp32 -> fp16 ----------------
__global__ void convert_x_kernel(const float4* __restrict__ x) {
    size_t i = (size_t)blockIdx.x * 256 + threadIdx.x;   // over MM*KK/4 float4 groups
    float4 v = x[i];
    __half2 h01 = __floats2half2_rn(v.x, v.y);
    __half2 h23 = __floats2half2_rn(v.z, v.w);
    __half2* dst = reinterpret_cast<__half2*>(g_A) + i * 2;
    dst[0] = h01;
    dst[1] = h23;
}

// ---------------- Kernel 3: pipelined HMMA GEMM + fused epilogue ----------------
__device__ __forceinline__ void load_stage(uint32_t sbase, int kk, int mt, int nt, int tid) {
    int row = tid >> 2;            // 0..63
    int chunk = tid & 3;           // 16B chunk within 64B row
    const __half* gA = g_A + (size_t)(mt * BM + row) * KK + kk * BK + chunk * 8;
    uint32_t da = sbase + (uint32_t)(row * (ROWPAD * 2) + chunk * 16);
    CP16(da, gA);
    CP16(da + 64 * (ROWPAD * 2), gA + (size_t)64 * KK);
    const __half* gB = g_W + (size_t)(nt * BN + row) * KK + kk * BK + chunk * 8;
    uint32_t db = sbase + A_STAGE_BYTES + (uint32_t)(row * (ROWPAD * 2) + chunk * 16);
#pragma unroll
    for (int i = 0; i < 4; i++)
        CP16(db + i * 64 * (ROWPAD * 2), gB + (size_t)i * 64 * KK);
}

__global__ void __launch_bounds__(256, 1)
gemm_kernel(const float* __restrict__ alpha, const float* __restrict__ bias,
            float* __restrict__ out) {
    extern __shared__ __align__(16) char smem[];
    uint32_t sb = smem_u32(smem);
    int tid = threadIdx.x, lane = tid & 31, wid = tid >> 5;
    int wm = wid & 1;              // 2 warps along M
    int wn = wid >> 1;             // 4 warps along N
    int cid = blockIdx.x;
    int nt = cid & 15;             // 16 N-tiles of 256
    int mt = cid >> 4;             // 64 M-tiles of 128

    // prologue: stages 0,1
    load_stage(sb, 0, mt, nt, tid);              CP_COMMIT();
    load_stage(sb + STAGE_BYTES, 1, mt, nt, tid); CP_COMMIT();

    float acc[4][8][4];
#pragma unroll
    for (int i = 0; i < 4; i++)
#pragma unroll
        for (int j = 0; j < 8; j++)
#pragma unroll
            for (int k = 0; k < 4; k++) acc[i][j][k] = 0.f;

    // per-lane ldmatrix base offsets (bytes)
    uint32_t aoff = (uint32_t)(((wm * 64 + (lane & 15)) * ROWPAD + (lane >> 4) * 8) * 2);
    int bg = lane >> 3;  // 0..3
    uint32_t boff = (uint32_t)(((wn * 64 + (bg & 1) * 8 + (lane & 7)) * ROWPAD + (bg >> 1) * 8) * 2);

    for (int kk = 0; kk < KITERS; kk++) {
        CP_WAIT(1);
        __syncthreads();
        if (kk + 2 < KITERS)
            load_stage(sb + (uint32_t)((kk + 2) % STAGES) * STAGE_BYTES, kk + 2, mt, nt, tid);
        CP_COMMIT();

        uint32_t stA = sb + (uint32_t)(kk % STAGES) * STAGE_BYTES;
        uint32_t stB = stA + A_STAGE_BYTES;
#pragma unroll
        for (int ks = 0; ks < 2; ks++) {
            uint32_t a[4][4], b[8][2];
#pragma unroll
            for (int mi = 0; mi < 4; mi++)
                ldsm_x4(a[mi][0], a[mi][1], a[mi][2], a[mi][3],
                        stA + aoff + mi * (16 * ROWPAD * 2) + ks * 32);
#pragma unroll
            for (int nj = 0; nj < 4; nj++) {
                uint32_t r0, r1, r2, r3;
                // B operand is col-major (k-contiguous per n) == W's [O][K] layout:
                // non-transposed ldmatrix gives the exact fragment.
                ldsm_x4(r0, r1, r2, r3, stB + boff + nj * (16 * ROWPAD * 2) + ks * 32);
                b[2*nj][0] = r0; b[2*nj][1] = r2;
                b[2*nj+1][0] = r1; b[2*nj+1][1] = r3;
            }
#pragma unroll
            for (int mi = 0; mi < 4; mi++)
#pragma unroll
                for (int ni = 0; ni < 8; ni++)
                    mma16816(acc[mi][ni], a[mi], b[ni]);
        }
    }

    // epilogue: y = acc*alpha + bias
    int colbase = nt * BN + wn * 64;
    int rowbase = mt * BM + wm * 64;
#pragma unroll
    for (int ni = 0; ni < 8; ni++) {
        int col = colbase + ni * 8 + (lane & 3) * 2;
        float2 av = *reinterpret_cast<const float2*>(alpha + col);
        float2 bv = *reinterpret_cast<const float2*>(bias + col);
#pragma unroll
        for (int mi = 0; mi < 4; mi++) {
            int r0 = rowbase + mi * 16 + (lane >> 2);
            float2 v0, v1;
            v0.x = acc[mi][ni][0] * av.x + bv.x;
            v0.y = acc[mi][ni][1] * av.y + bv.y;
            v1.x = acc[mi][ni][2] * av.x + bv.x;
            v1.y = acc[mi][ni][3] * av.y + bv.y;
            *reinterpret_cast<float2*>(out + (size_t)r0 * OO + col) = v0;
            *reinterpret_cast<float2*>(out + (size_t)(r0 + 8) * OO + col) = v1;
        }
    }
}

// ---------------- host ----------------
extern "C" void kernel_launch(void* const* d_in, const int* in_sizes, int n_in,
                              void* d_out, int out_size) {
    const float* x     = (const float*)d_in[0];
    const int*   nz    = (const int*)d_in[1];
    const int*   sgn   = (const int*)d_in[2];
    const float* bias  = (const float*)d_in[3];
    const float* alpha = (const float*)d_in[4];
    float* out = (float*)d_out;

    unpack_w_kernel<<<(OO * (KK / 32)) / 256, 256>>>(nz, sgn);
    convert_x_kernel<<<(int)(((size_t)MM * KK / 4) / 256), 256>>>((const float4*)x);

    cudaFuncSetAttribute(gemm_kernel, cudaFuncAttributeMaxDynamicSharedMemorySize, SMEM_BYTES);

    gemm_kernel<<<(MM / BM) * (OO / BN), 256, SMEM_BYTES>>>(alpha, bias, out);
}

// round 10
// speedup vs baseline: 1.1479x; 1.1479x over previous
#include <cuda_runtime.h>
#include <cuda_fp16.h>
#include <cstdint>
#include <cstddef>

#define MM 8192
#define KK 4096
#define OO 4096

#define BM 128
#define BN 256
#define BK 64
#define KITERS (KK / BK)        // 64
#define STAGES 3
#define ROWPAD 72               // halves per row (64 data + 8 pad): 144B stride, conflict-free
#define A_STAGE_BYTES (BM * ROWPAD * 2)           // 18432
#define B_STAGE_BYTES (BN * ROWPAD * 2)           // 36864
#define STAGE_BYTES   (A_STAGE_BYTES + B_STAGE_BYTES)  // 55296
#define SMEM_BYTES    (STAGES * STAGE_BYTES)      // 165888

// Scratch (device globals only -- no allocation allowed)
__device__ __half g_W[(size_t)OO * KK];   // 32 MB dense ternary weights (fp16 exact)
__device__ __half g_A[(size_t)MM * KK];   // 64 MB x in fp16

// ---------------- PTX helpers (base sm_103 features only) ----------------
__device__ __forceinline__ uint32_t smem_u32(const void* p) {
    uint32_t a;
    asm("{ .reg .u64 t; cvta.to.shared.u64 t, %1; cvt.u32.u64 %0, t; }" : "=r"(a) : "l"(p));
    return a;
}
#define CP16(dst, src) \
    asm volatile("cp.async.cg.shared.global [%0], [%1], 16;" :: "r"(dst), "l"(src) : "memory")
#define CP_COMMIT() asm volatile("cp.async.commit_group;" ::: "memory")
#define CP_WAIT(n)  asm volatile("cp.async.wait_group %0;" :: "n"(n) : "memory")

__device__ __forceinline__ void ldsm_x4(uint32_t& r0, uint32_t& r1, uint32_t& r2, uint32_t& r3,
                                        uint32_t addr) {
    asm volatile("ldmatrix.sync.aligned.m8n8.x4.shared.b16 {%0,%1,%2,%3}, [%4];"
                 : "=r"(r0), "=r"(r1), "=r"(r2), "=r"(r3) : "r"(addr));
}
__device__ __forceinline__ void mma16816(float* c, const uint32_t* a, const uint32_t* b) {
    asm volatile(
        "mma.sync.aligned.m16n8k16.row.col.f32.f16.f16.f32 "
        "{%0,%1,%2,%3}, {%4,%5,%6,%7}, {%8,%9}, {%0,%1,%2,%3};"
        : "+f"(c[0]), "+f"(c[1]), "+f"(c[2]), "+f"(c[3])
        : "r"(a[0]), "r"(a[1]), "r"(a[2]), "r"(a[3]), "r"(b[0]), "r"(b[1]));
}

// ---------------- Kernel 1: unpack ternary -> fp16 W ----------------
__global__ void unpack_w_kernel(const int* __restrict__ nz, const int* __restrict__ sgn) {
    int idx = blockIdx.x * 256 + threadIdx.x;      // word index, OO*KK/32 total
    uint32_t nzv = (uint32_t)nz[idx];
    uint32_t sgv = (uint32_t)sgn[idx];
    uint32_t packed[16];
#pragma unroll
    for (int j = 0; j < 16; j++) {
        uint32_t lo = ((nzv >> (2*j)) & 1u)   ? (((sgv >> (2*j)) & 1u)   ? 0xBC00u : 0x3C00u) : 0u;
        uint32_t hi = ((nzv >> (2*j+1)) & 1u) ? (((sgv >> (2*j+1)) & 1u) ? 0xBC00u : 0x3C00u) : 0u;
        packed[j] = lo | (hi << 16);
    }
    uint4* dst = reinterpret_cast<uint4*>(g_W + (size_t)idx * 32);
#pragma unroll
    for (int j = 0; j < 4; j++)
        dst[j] = make_uint4(packed[4*j], packed[4*j+1], packed[4*j+2], packed[4*j+3]);
}

// ---------------- Kernel 2: x fp32 -> fp16 ----------------
__global__ void convert_x_kernel(const float4* __restrict__ x) {
    size_t i = (size_t)blockIdx.x * 256 + threadIdx.x;   // over MM*KK/4 float4 groups
    float4 v = x[i];
    __half2 h01 = __floats2half2_rn(v.x, v.y);
    __half2 h23 = __floats2half2_rn(v.z, v.w);
    __half2* dst = reinterpret_cast<__half2*>(g_A) + i * 2;
    dst[0] = h01;
    dst[1] = h23;
}

// ---------------- Kernel 3: pipelined HMMA GEMM + fused epilogue ----------------
__global__ void __launch_bounds__(256, 1)
gemm_kernel(const float* __restrict__ alpha, const float* __restrict__ bias,
            float* __restrict__ out) {
    extern __shared__ __align__(16) char smem[];
    uint32_t sb = smem_u32(smem);
    int tid = threadIdx.x, lane = tid & 31, wid = tid >> 5;
    int wm = wid & 1;              // 2 warps along M
    int wn = wid >> 1;             // 4 warps along N
    int cid = blockIdx.x;
    int nt = cid & 15;             // 16 N-tiles of 256
    int mt = cid >> 4;             // 64 M-tiles of 128

    // loader mapping: r = tid>>3 (0..31), c = tid&7 (16B chunk of 128B row)
    int lr = tid >> 3, lc = tid & 7;
    const __half* baseA = g_A + (size_t)(mt * BM + lr) * KK + lc * 8;
    const __half* baseB = g_W + (size_t)(nt * BN + lr) * KK + lc * 8;
    uint32_t sA = sb + (uint32_t)(lr * (ROWPAD * 2) + lc * 16);
    uint32_t sB = sb + A_STAGE_BYTES + (uint32_t)(lr * (ROWPAD * 2) + lc * 16);

#define LOAD_STAGE(st, kk) do { \
    uint32_t _so = (uint32_t)(st) * STAGE_BYTES; \
    const __half* _ga = baseA + (kk) * BK; \
    const __half* _gb = baseB + (kk) * BK; \
    CP16(sA + _so,                          _ga); \
    CP16(sA + _so + 32*(ROWPAD*2),          _ga + (size_t)32*KK); \
    CP16(sA + _so + 64*(ROWPAD*2),          _ga + (size_t)64*KK); \
    CP16(sA + _so + 96*(ROWPAD*2),          _ga + (size_t)96*KK); \
    CP16(sB + _so,                          _gb); \
    CP16(sB + _so + 32*(ROWPAD*2),          _gb + (size_t)32*KK); \
    CP16(sB + _so + 64*(ROWPAD*2),          _gb + (size_t)64*KK); \
    CP16(sB + _so + 96*(ROWPAD*2),          _gb + (size_t)96*KK); \
    CP16(sB + _so + 128*(ROWPAD*2),         _gb + (size_t)128*KK); \
    CP16(sB + _so + 160*(ROWPAD*2),         _gb + (size_t)160*KK); \
    CP16(sB + _so + 192*(ROWPAD*2),         _gb + (size_t)192*KK); \
    CP16(sB + _so + 224*(ROWPAD*2),         _gb + (size_t)224*KK); \
} while (0)

    // prologue: stages 0,1
    LOAD_STAGE(0, 0); CP_COMMIT();
    LOAD_STAGE(1, 1); CP_COMMIT();

    float acc[4][8][4];
#pragma unroll
    for (int i = 0; i < 4; i++)
#pragma unroll
        for (int j = 0; j < 8; j++)
#pragma unroll
            for (int k = 0; k < 4; k++) acc[i][j][k] = 0.f;

    // per-lane ldmatrix base offsets (bytes)
    uint32_t aoff = (uint32_t)(((wm * 64 + (lane & 15)) * ROWPAD + (lane >> 4) * 8) * 2);
    int bg = lane >> 3;  // 0..3
    uint32_t boff = (uint32_t)(((wn * 64 + (bg & 1) * 8 + (lane & 7)) * ROWPAD + (bg >> 1) * 8) * 2);

    int st = 0;
    for (int kk = 0; kk < KITERS; kk++) {
        CP_WAIT(1);
        __syncthreads();
        if (kk + 2 < KITERS) {
            int wst = st + 2; if (wst >= STAGES) wst -= STAGES;
            LOAD_STAGE(wst, kk + 2);
        }
        CP_COMMIT();

        uint32_t stA = sb + (uint32_t)st * STAGE_BYTES;
        uint32_t stB = stA + A_STAGE_BYTES;
#pragma unroll
        for (int ks = 0; ks < 4; ks++) {
            uint32_t a[4][4], b[8][2];
#pragma unroll
            for (int mi = 0; mi < 4; mi++)
                ldsm_x4(a[mi][0], a[mi][1], a[mi][2], a[mi][3],
                        stA + aoff + mi * (16 * ROWPAD * 2) + ks * 32);
#pragma unroll
            for (int nj = 0; nj < 4; nj++) {
                uint32_t r0, r1, r2, r3;
                // B operand is col-major (k-contiguous per n) == W's [O][K] layout
                ldsm_x4(r0, r1, r2, r3, stB + boff + nj * (16 * ROWPAD * 2) + ks * 32);
                b[2*nj][0] = r0; b[2*nj][1] = r2;
                b[2*nj+1][0] = r1; b[2*nj+1][1] = r3;
            }
#pragma unroll
            for (int mi = 0; mi < 4; mi++)
#pragma unroll
                for (int ni = 0; ni < 8; ni++)
                    mma16816(acc[mi][ni], a[mi], b[ni]);
        }
        if (++st == STAGES) st = 0;
    }

    // epilogue: y = acc*alpha + bias
    int colbase = nt * BN + wn * 64;
    int rowbase = mt * BM + wm * 64;
#pragma unroll
    for (int ni = 0; ni < 8; ni++) {
        int col = colbase + ni * 8 + (lane & 3) * 2;
        float2 av = *reinterpret_cast<const float2*>(alpha + col);
        float2 bv = *reinterpret_cast<const float2*>(bias + col);
#pragma unroll
        for (int mi = 0; mi < 4; mi++) {
            int r0 = rowbase + mi * 16 + (lane >> 2);
            float2 v0, v1;
            v0.x = acc[mi][ni][0] * av.x + bv.x;
            v0.y = acc[mi][ni][1] * av.y + bv.y;
            v1.x = acc[mi][ni][2] * av.x + bv.x;
            v1.y = acc[mi][ni][3] * av.y + bv.y;
            *reinterpret_cast<float2*>(out + (size_t)r0 * OO + col) = v0;
            *reinterpret_cast<float2*>(out + (size_t)(r0 + 8) * OO + col) = v1;
        }
    }
#undef LOAD_STAGE
}

// ---------------- host ----------------
extern "C" void kernel_launch(void* const* d_in, const int* in_sizes, int n_in,
                              void* d_out, int out_size) {
    const float* x     = (const float*)d_in[0];
    const int*   nz    = (const int*)d_in[1];
    const int*   sgn   = (const int*)d_in[2];
    const float* bias  = (const float*)d_in[3];
    const float* alpha = (const float*)d_in[4];
    float* out = (float*)d_out;

    unpack_w_kernel<<<(OO * (KK / 32)) / 256, 256>>>(nz, sgn);
    convert_x_kernel<<<(int)(((size_t)MM * KK / 4) / 256), 256>>>((const float4*)x);

    cudaFuncSetAttribute(gemm_kernel, cudaFuncAttributeMaxDynamicSharedMemorySize, SMEM_BYTES);

    gemm_kernel<<<(MM / BM) * (OO / BN), 256, SMEM_BYTES>>>(alpha, bias, out);
}